// round 2
// baseline (speedup 1.0000x reference)
#include <cuda_runtime.h>
#include <cuda_bf16.h>

// ---------------------------------------------------------------------------
// DeformableConvBlock: offset conv -> deformable sample+conv -> BN -> +1x1 -> relu
// B=8, CIN=128, COUT=256, H=W=64
// ---------------------------------------------------------------------------

#define B_   8
#define CIN_ 128
#define COUT_ 256
#define H_ 64
#define W_ 64
#define HW_ 4096
#define KTOT 1152            // CIN*9
#define EPS_ 1e-5f

// Scratch (device globals: allocation-free rule)
__device__ float g_off[B_ * 18 * HW_];          // offsets [B,18,H,W]
__device__ float g_y[B_ * COUT_ * HW_];         // pre-BN main conv output
__device__ float g_scale[COUT_];
__device__ float g_shift[COUT_];

// ---- f32x2 helpers ----
__device__ __forceinline__ unsigned long long pack2(float a, float b) {
    unsigned long long r;
    asm("mov.b64 %0, {%1, %2};" : "=l"(r)
        : "r"(__float_as_uint(a)), "r"(__float_as_uint(b)));
    return r;
}
__device__ __forceinline__ float2 unpack2(unsigned long long v) {
    unsigned int a, b;
    asm("mov.b64 {%0, %1}, %2;" : "=r"(a), "=r"(b) : "l"(v));
    return make_float2(__uint_as_float(a), __uint_as_float(b));
}
__device__ __forceinline__ void fma2(unsigned long long& d,
                                     unsigned long long a, unsigned long long b) {
    asm("fma.rn.f32x2 %0, %1, %2, %0;" : "+l"(d) : "l"(a), "l"(b));
}

// ===========================================================================
// Kernel 1: offset conv  (3x3, pad 1, CIN=128 -> 18)
// grid (16, 8): blockIdx.x = row quad, blockIdx.y = image. 256 threads.
// dynamic smem: ws[128*9*18] repacked weights + xtile[6*66]
// ===========================================================================
__global__ __launch_bounds__(256, 1)
void k_offset(const float* __restrict__ x, const float* __restrict__ w_off,
              const float* __restrict__ b_off) {
    extern __shared__ float sm1[];
    float* ws = sm1;                 // [ (cin*9+k)*18 + co ], 20736 floats
    float* xt = sm1 + 20736;         // [6][66]

    const int tid = threadIdx.x;
    const int b   = blockIdx.y;
    const int h0  = blockIdx.x * 4;

    // repack w_off [18][128][9] -> ws[(cin*9+k)][18]
    for (int i = tid; i < 18 * CIN_ * 9; i += 256) {
        int co  = i / (CIN_ * 9);
        int r   = i - co * (CIN_ * 9);
        int cin = r / 9;
        int k   = r - cin * 9;
        ws[(cin * 9 + k) * 18 + co] = w_off[i];
    }
    __syncthreads();

    const int rt = tid >> 6;     // 0..3 row in quad
    const int wc = tid & 63;     // column

    unsigned long long acc[9];
#pragma unroll
    for (int m = 0; m < 9; ++m) acc[m] = 0ull;

    const float* xb = x + ((size_t)b * CIN_) * HW_;

    for (int cin = 0; cin < CIN_; ++cin) {
        // load x tile rows h0-1..h0+4, cols -1..64
        const float* xc = xb + (size_t)cin * HW_;
        for (int i = tid; i < 6 * 66; i += 256) {
            int r  = i / 66;
            int cc = i - r * 66;
            int gy = h0 - 1 + r;
            int gx = cc - 1;
            float v = 0.f;
            if (gy >= 0 && gy < H_ && gx >= 0 && gx < W_) v = xc[gy * W_ + gx];
            xt[i] = v;
        }
        __syncthreads();

        float xv[9];
#pragma unroll
        for (int ky = 0; ky < 3; ++ky)
#pragma unroll
            for (int kx = 0; kx < 3; ++kx)
                xv[ky * 3 + kx] = xt[(rt + ky) * 66 + (wc + kx)];

#pragma unroll
        for (int k = 0; k < 9; ++k) {
            const unsigned long long* wp =
                (const unsigned long long*)(ws) + (size_t)(cin * 9 + k) * 9;
            unsigned long long x2 = pack2(xv[k], xv[k]);
#pragma unroll
            for (int m = 0; m < 9; ++m) fma2(acc[m], wp[m], x2);
        }
        __syncthreads();
    }

    float* ob = g_off + ((size_t)b * 18) * HW_ + (h0 + rt) * W_ + wc;
#pragma unroll
    for (int m = 0; m < 9; ++m) {
        float2 v = unpack2(acc[m]);
        ob[(2 * m) * HW_]     = v.x + b_off[2 * m];
        ob[(2 * m + 1) * HW_] = v.y + b_off[2 * m + 1];
    }
}

// ===========================================================================
// Kernel 2: deformable sample + main conv  -> g_y
// One block = 32 pixels (half a row) of one image, 256 threads (one per cout).
// dynamic smem: samp[1152][32] + w_s[256][33] + taps
// ===========================================================================
#define PIX 32
#define KK_CHUNK 32

__global__ __launch_bounds__(256, 1)
void k_main(const float* __restrict__ x, const float* __restrict__ w_def,
            const float* __restrict__ b_def) {
    extern __shared__ float sm2[];
    float*  samp  = sm2;                                  // 1152*32 floats
    float*  w_s   = sm2 + KTOT * PIX;                     // 256*33 floats
    int4*   tap_a = (int4*)(w_s + COUT_ * 33);            // 288 int4
    float4* tap_w = (float4*)(tap_a + PIX * 9);           // 288 float4

    const int tid   = threadIdx.x;
    const int tile  = blockIdx.x;        // 0..1023
    const int bimg  = tile >> 7;
    const int t128  = tile & 127;
    const int h     = t128 >> 1;
    const int wbase = (t128 & 1) * 32;

    // ---- Phase A0: per-(pixel,tap) bilinear metadata ----
    for (int idx = tid; idx < PIX * 9; idx += 256) {
        int p = idx / 9;
        int k = idx - p * 9;
        int wpix = wbase + p;
        const float* offb = g_off + ((size_t)bimg * 18) * HW_ + h * W_ + wpix;
        float dy = offb[(size_t)(2 * k) * HW_];
        float dx = offb[(size_t)(2 * k + 1) * HW_];
        float py = (float)(h + (k / 3) - 1) + dy;
        float px = (float)(wpix + (k % 3) - 1) + dx;
        float y0 = floorf(py), x0 = floorf(px);
        float fy = py - y0,    fx = px - x0;
        int iy = (int)y0, ix = (int)x0;
        float w00 = (1.f - fy) * (1.f - fx);
        float w01 = (1.f - fy) * fx;
        float w10 = fy * (1.f - fx);
        float w11 = fy * fx;
        int4 ad; float4 wt;
        bool vy0 = (iy >= 0)     && (iy < H_);
        bool vy1 = (iy + 1 >= 0) && (iy + 1 < H_);
        bool vx0 = (ix >= 0)     && (ix < W_);
        bool vx1 = (ix + 1 >= 0) && (ix + 1 < W_);
        ad.x = (vy0 && vx0) ? (iy * W_ + ix)           : 0;  wt.x = (vy0 && vx0) ? w00 : 0.f;
        ad.y = (vy0 && vx1) ? (iy * W_ + ix + 1)       : 0;  wt.y = (vy0 && vx1) ? w01 : 0.f;
        ad.z = (vy1 && vx0) ? ((iy + 1) * W_ + ix)     : 0;  wt.z = (vy1 && vx0) ? w10 : 0.f;
        ad.w = (vy1 && vx1) ? ((iy + 1) * W_ + ix + 1) : 0;  wt.w = (vy1 && vx1) ? w11 : 0.f;
        tap_a[idx] = ad;
        tap_w[idx] = wt;
    }
    __syncthreads();

    // ---- Phase A1: gather samp[kk][p] ----
    const float* xb = x + ((size_t)bimg * CIN_) * HW_;
#pragma unroll 4
    for (int e = tid; e < KTOT * PIX; e += 256) {
        int p  = e & 31;
        int kk = e >> 5;          // = c*9 + k
        int c  = kk / 9;
        int k  = kk - c * 9;
        int ti = p * 9 + k;
        int4   ad = tap_a[ti];
        float4 wt = tap_w[ti];
        const float* xc = xb + (size_t)c * HW_;
        float v = wt.x * __ldg(xc + ad.x) + wt.y * __ldg(xc + ad.y)
                + wt.z * __ldg(xc + ad.z) + wt.w * __ldg(xc + ad.w);
        samp[e] = v;
    }
    __syncthreads();

    // ---- Phase B: GEMM, thread tid = cout, 16 f32x2 pixel-pair accumulators ----
    unsigned long long acc[16];
    {
        float bias = __ldg(b_def + tid);
        unsigned long long b2 = pack2(bias, bias);
#pragma unroll
        for (int m = 0; m < 16; ++m) acc[m] = b2;
    }

    for (int kk0 = 0; kk0 < KTOT; kk0 += KK_CHUNK) {
        // stage w_def[:, kk0:kk0+32] into padded smem
        for (int i = tid; i < COUT_ * (KK_CHUNK / 4); i += 256) {
            int c  = i >> 3;
            int j4 = i & 7;
            float4 v = *(const float4*)(w_def + (size_t)c * KTOT + kk0 + j4 * 4);
            float* dst = w_s + c * 33 + j4 * 4;
            dst[0] = v.x; dst[1] = v.y; dst[2] = v.z; dst[3] = v.w;
        }
        __syncthreads();

        const float* wr = w_s + tid * 33;
#pragma unroll 4
        for (int j = 0; j < KK_CHUNK; ++j) {
            float wv = wr[j];
            unsigned long long w2 = pack2(wv, wv);
            const ulonglong2* srow = (const ulonglong2*)(samp + (size_t)(kk0 + j) * PIX);
#pragma unroll
            for (int q = 0; q < 8; ++q) {
                ulonglong2 s = srow[q];
                fma2(acc[2 * q],     w2, s.x);
                fma2(acc[2 * q + 1], w2, s.y);
            }
        }
        __syncthreads();
    }

    // ---- epilogue: write y ----
    float* yb = g_y + ((size_t)(bimg * COUT_ + tid)) * HW_ + h * W_ + wbase;
#pragma unroll
    for (int q = 0; q < 8; ++q) {
        float2 a = unpack2(acc[2 * q]);
        float2 b = unpack2(acc[2 * q + 1]);
        float4 v = make_float4(a.x, a.y, b.x, b.y);
        *(float4*)(yb + 4 * q) = v;
    }
}

// ===========================================================================
// Kernel 3: BN batch stats -> g_scale/g_shift. One block per channel.
// ===========================================================================
__global__ __launch_bounds__(256)
void k_stats(const float* __restrict__ gamma, const float* __restrict__ beta) {
    const int co = blockIdx.x;
    const int t  = threadIdx.x;
    float s = 0.f, s2 = 0.f;
    for (int b = 0; b < B_; ++b) {
        const float* yb = g_y + ((size_t)(b * COUT_ + co)) * HW_;
        for (int i = t * 4; i < HW_; i += 1024) {
            float4 v = *(const float4*)(yb + i);
            s  += v.x + v.y + v.z + v.w;
            s2 += v.x * v.x + v.y * v.y + v.z * v.z + v.w * v.w;
        }
    }
    __shared__ float rs[256], rq[256];
    rs[t] = s; rq[t] = s2;
    __syncthreads();
    for (int off = 128; off; off >>= 1) {
        if (t < off) { rs[t] += rs[t + off]; rq[t] += rq[t + off]; }
        __syncthreads();
    }
    if (t == 0) {
        const float inv_n = 1.f / (float)(B_ * HW_);
        float mean = rs[0] * inv_n;
        float var  = rq[0] * inv_n - mean * mean;
        float istd = rsqrtf(var + EPS_);
        float g = gamma[co];
        g_scale[co] = g * istd;
        g_shift[co] = beta[co] - mean * g * istd;
    }
}

// ===========================================================================
// Kernel 4: normalize + 1x1 shortcut + relu -> out
// One block = 32 pixels, 256 threads (one per cout).
// ===========================================================================
__global__ __launch_bounds__(256, 1)
void k_final(const float* __restrict__ x, const float* __restrict__ w_sc,
             const float* __restrict__ b_sc, float* __restrict__ out) {
    __shared__ __align__(16) float xs[CIN_ * PIX];   // [c][32]

    const int tid   = threadIdx.x;
    const int tile  = blockIdx.x;
    const int bimg  = tile >> 7;
    const int t128  = tile & 127;
    const int h     = t128 >> 1;
    const int wbase = (t128 & 1) * 32;

    const float* xb = x + ((size_t)bimg * CIN_) * HW_ + h * W_ + wbase;
    for (int i = tid; i < CIN_ * PIX; i += 256) {
        int c = i >> 5;
        int p = i & 31;
        xs[i] = xb[(size_t)c * HW_ + p];
    }
    __syncthreads();

    unsigned long long acc[16];
    {
        float bias = __ldg(b_sc + tid);
        unsigned long long b2 = pack2(bias, bias);
#pragma unroll
        for (int m = 0; m < 16; ++m) acc[m] = b2;
    }

    const float* wrow = w_sc + (size_t)tid * CIN_;
#pragma unroll 4
    for (int c4 = 0; c4 < CIN_ / 4; ++c4) {
        float4 wv = *(const float4*)(wrow + c4 * 4);
        float wl[4] = {wv.x, wv.y, wv.z, wv.w};
#pragma unroll
        for (int cc = 0; cc < 4; ++cc) {
            unsigned long long w2 = pack2(wl[cc], wl[cc]);
            const ulonglong2* srow = (const ulonglong2*)(xs + (c4 * 4 + cc) * PIX);
#pragma unroll
            for (int q = 0; q < 8; ++q) {
                ulonglong2 s = srow[q];
                fma2(acc[2 * q],     w2, s.x);
                fma2(acc[2 * q + 1], w2, s.y);
            }
        }
    }

    const float sc = g_scale[tid];
    const float sh = g_shift[tid];
    const size_t o = ((size_t)(bimg * COUT_ + tid)) * HW_ + h * W_ + wbase;
#pragma unroll
    for (int q = 0; q < 8; ++q) {
        float4 yv = *(const float4*)(g_y + o + 4 * q);
        float2 a = unpack2(acc[2 * q]);
        float2 b = unpack2(acc[2 * q + 1]);
        float4 r;
        r.x = fmaxf(yv.x * sc + sh + a.x, 0.f);
        r.y = fmaxf(yv.y * sc + sh + a.y, 0.f);
        r.z = fmaxf(yv.z * sc + sh + b.x, 0.f);
        r.w = fmaxf(yv.w * sc + sh + b.y, 0.f);
        *(float4*)(out + o + 4 * q) = r;
    }
}

// ===========================================================================
extern "C" void kernel_launch(void* const* d_in, const int* in_sizes, int n_in,
                              void* d_out, int out_size) {
    const float* x     = (const float*)d_in[0];
    const float* w_off = (const float*)d_in[1];
    const float* b_off = (const float*)d_in[2];
    const float* w_def = (const float*)d_in[3];
    const float* b_def = (const float*)d_in[4];
    const float* gamma = (const float*)d_in[5];
    const float* beta  = (const float*)d_in[6];
    const float* w_sc  = (const float*)d_in[7];
    const float* b_sc  = (const float*)d_in[8];
    float* out = (float*)d_out;

    const int smem1 = (20736 + 6 * 66) * 4;                       // ~84.6 KB
    const int smem2 = (KTOT * PIX + COUT_ * 33) * 4
                    + PIX * 9 * (sizeof(int4) + sizeof(float4));  // ~190.5 KB

    cudaFuncSetAttribute(k_offset, cudaFuncAttributeMaxDynamicSharedMemorySize, smem1);
    cudaFuncSetAttribute(k_main,   cudaFuncAttributeMaxDynamicSharedMemorySize, smem2);

    k_offset<<<dim3(16, 8), 256, smem1>>>(x, w_off, b_off);
    k_main<<<1024, 256, smem2>>>(x, w_def, b_def);
    k_stats<<<256, 256>>>(gamma, beta);
    k_final<<<1024, 256>>>(x, w_sc, b_sc, out);
}

// round 3
// speedup vs baseline: 1.0876x; 1.0876x over previous
#include <cuda_runtime.h>
#include <cuda_bf16.h>

// ---------------------------------------------------------------------------
// DeformableConvBlock: offset conv -> deformable sample+conv -> BN -> +1x1 -> relu
// B=8, CIN=128, COUT=256, H=W=64
// ---------------------------------------------------------------------------

#define B_   8
#define CIN_ 128
#define COUT_ 256
#define H_ 64
#define W_ 64
#define HW_ 4096
#define KTOT 1152            // CIN*9
#define EPS_ 1e-5f

#define PIX2 64              // pixels per block in k_main / k_final (one row)
#define CCH  8               // cin per K-chunk in k_main
#define KCH  (CCH * 9)       // 72 k-values per chunk

// Scratch (device globals: allocation-free rule)
__device__ float g_off[B_ * 18 * HW_];          // offsets [B,18,H,W]
__device__ float g_y[B_ * COUT_ * HW_];         // pre-BN main conv output
__device__ float g_scale[COUT_];
__device__ float g_shift[COUT_];

// ---- f32x2 helpers ----
__device__ __forceinline__ unsigned long long pack2(float a, float b) {
    unsigned long long r;
    asm("mov.b64 %0, {%1, %2};" : "=l"(r)
        : "r"(__float_as_uint(a)), "r"(__float_as_uint(b)));
    return r;
}
__device__ __forceinline__ float2 unpack2(unsigned long long v) {
    unsigned int a, b;
    asm("mov.b64 {%0, %1}, %2;" : "=r"(a), "=r"(b) : "l"(v));
    return make_float2(__uint_as_float(a), __uint_as_float(b));
}
__device__ __forceinline__ void fma2(unsigned long long& d,
                                     unsigned long long a, unsigned long long b) {
    asm("fma.rn.f32x2 %0, %1, %2, %0;" : "+l"(d) : "l"(a), "l"(b));
}

// ===========================================================================
// Kernel 1: offset conv  (3x3, pad 1, CIN=128 -> 18)
// grid (16, 8): blockIdx.x = row quad, blockIdx.y = image. 256 threads.
// ===========================================================================
__global__ __launch_bounds__(256, 1)
void k_offset(const float* __restrict__ x, const float* __restrict__ w_off,
              const float* __restrict__ b_off) {
    extern __shared__ float sm1[];
    float* ws = sm1;                 // [ (cin*9+k)*18 + co ], 20736 floats
    float* xt = sm1 + 20736;         // [6][66]

    const int tid = threadIdx.x;
    const int b   = blockIdx.y;
    const int h0  = blockIdx.x * 4;

    // repack w_off [18][128][9] -> ws[(cin*9+k)][18]
    for (int i = tid; i < 18 * CIN_ * 9; i += 256) {
        int co  = i / (CIN_ * 9);
        int r   = i - co * (CIN_ * 9);
        int cin = r / 9;
        int k   = r - cin * 9;
        ws[(cin * 9 + k) * 18 + co] = w_off[i];
    }
    __syncthreads();

    const int rt = tid >> 6;     // 0..3 row in quad
    const int wc = tid & 63;     // column

    unsigned long long acc[9];
#pragma unroll
    for (int m = 0; m < 9; ++m) acc[m] = 0ull;

    const float* xb = x + ((size_t)b * CIN_) * HW_;

    for (int cin = 0; cin < CIN_; ++cin) {
        const float* xc = xb + (size_t)cin * HW_;
        for (int i = tid; i < 6 * 66; i += 256) {
            int r  = i / 66;
            int cc = i - r * 66;
            int gy = h0 - 1 + r;
            int gx = cc - 1;
            float v = 0.f;
            if (gy >= 0 && gy < H_ && gx >= 0 && gx < W_) v = xc[gy * W_ + gx];
            xt[i] = v;
        }
        __syncthreads();

        float xv[9];
#pragma unroll
        for (int ky = 0; ky < 3; ++ky)
#pragma unroll
            for (int kx = 0; kx < 3; ++kx)
                xv[ky * 3 + kx] = xt[(rt + ky) * 66 + (wc + kx)];

#pragma unroll
        for (int k = 0; k < 9; ++k) {
            const unsigned long long* wp =
                (const unsigned long long*)(ws) + (size_t)(cin * 9 + k) * 9;
            unsigned long long x2 = pack2(xv[k], xv[k]);
#pragma unroll
            for (int m = 0; m < 9; ++m) fma2(acc[m], wp[m], x2);
        }
        __syncthreads();
    }

    float* ob = g_off + ((size_t)b * 18) * HW_ + (h0 + rt) * W_ + wc;
#pragma unroll
    for (int m = 0; m < 9; ++m) {
        float2 v = unpack2(acc[m]);
        ob[(2 * m) * HW_]     = v.x + b_off[2 * m];
        ob[(2 * m + 1) * HW_] = v.y + b_off[2 * m + 1];
    }
}

// ===========================================================================
// Kernel 2: deformable sample + main conv  -> g_y
// One block = one (image,row): 64 pixels. 256 threads (thread = cout).
// K-chunked: 8 cin (72 k) per chunk. smem ~37KB -> occupancy 2.
// Weights streamed per-thread from L2 (w_def row reused across 512 blocks).
// ===========================================================================
__global__ __launch_bounds__(256, 2)
void k_main(const float* __restrict__ x, const float* __restrict__ w_def,
            const float* __restrict__ b_def) {
    extern __shared__ float sm2[];
    float*  samp  = sm2;                                  // [72][64]
    int4*   tap_a = (int4*)(sm2 + KCH * PIX2);            // 576 int4
    float4* tap_w = (float4*)(tap_a + PIX2 * 9);          // 576 float4

    const int tid  = threadIdx.x;
    const int blk  = blockIdx.x;          // 0..511
    const int bimg = blk >> 6;
    const int h    = blk & 63;

    // ---- Phase A0: per-(pixel,tap) bilinear metadata (64*9 entries) ----
    for (int idx = tid; idx < PIX2 * 9; idx += 256) {
        int p = idx / 9;
        int k = idx - p * 9;
        const float* offb = g_off + ((size_t)bimg * 18) * HW_ + h * W_ + p;
        float dy = offb[(size_t)(2 * k) * HW_];
        float dx = offb[(size_t)(2 * k + 1) * HW_];
        float py = (float)(h + (k / 3) - 1) + dy;
        float px = (float)(p + (k % 3) - 1) + dx;
        float y0 = floorf(py), x0 = floorf(px);
        float fy = py - y0,    fx = px - x0;
        int iy = (int)y0, ix = (int)x0;
        float w00 = (1.f - fy) * (1.f - fx);
        float w01 = (1.f - fy) * fx;
        float w10 = fy * (1.f - fx);
        float w11 = fy * fx;
        int4 ad; float4 wt;
        bool vy0 = (iy >= 0)     && (iy < H_);
        bool vy1 = (iy + 1 >= 0) && (iy + 1 < H_);
        bool vx0 = (ix >= 0)     && (ix < W_);
        bool vx1 = (ix + 1 >= 0) && (ix + 1 < W_);
        ad.x = (vy0 && vx0) ? (iy * W_ + ix)           : 0;  wt.x = (vy0 && vx0) ? w00 : 0.f;
        ad.y = (vy0 && vx1) ? (iy * W_ + ix + 1)       : 0;  wt.y = (vy0 && vx1) ? w01 : 0.f;
        ad.z = (vy1 && vx0) ? ((iy + 1) * W_ + ix)     : 0;  wt.z = (vy1 && vx0) ? w10 : 0.f;
        ad.w = (vy1 && vx1) ? ((iy + 1) * W_ + ix + 1) : 0;  wt.w = (vy1 && vx1) ? w11 : 0.f;
        tap_a[idx] = ad;
        tap_w[idx] = wt;
    }

    // ---- acc init: 64 pixels as 32 f32x2 ----
    unsigned long long acc[32];
    {
        float bias = __ldg(b_def + tid);
        unsigned long long b2 = pack2(bias, bias);
#pragma unroll
        for (int m = 0; m < 32; ++m) acc[m] = b2;
    }

    const float*  xb    = x + ((size_t)bimg * CIN_) * HW_;
    const float4* wrow4 = (const float4*)(w_def + (size_t)tid * KTOT);

    __syncthreads();

    for (int c0 = 0; c0 < CIN_; c0 += CCH) {
        // ---- gather chunk: 72*64 = 4608 elems, 18 per thread ----
#pragma unroll
        for (int i = 0; i < 18; ++i) {
            int e  = tid + i * 256;
            int p  = e & 63;
            int kk = e >> 6;          // 0..71
            int c  = kk / 9;
            int k  = kk - c * 9;
            int ti = p * 9 + k;
            int4   ad = tap_a[ti];
            float4 wt = tap_w[ti];
            const float* xc = xb + (size_t)(c0 + c) * HW_;
            samp[e] = wt.x * __ldg(xc + ad.x) + wt.y * __ldg(xc + ad.y)
                    + wt.z * __ldg(xc + ad.z) + wt.w * __ldg(xc + ad.w);
        }
        __syncthreads();

        // ---- GEMM over the 72 k of this chunk ----
        const float4* wchunk = wrow4 + ((c0 * 9) >> 2);   // 18 float4
#pragma unroll 3
        for (int jj = 0; jj < KCH / 4; ++jj) {
            float4 wq = __ldg(wchunk + jj);
            float wl[4] = {wq.x, wq.y, wq.z, wq.w};
#pragma unroll
            for (int t = 0; t < 4; ++t) {
                unsigned long long w2 = pack2(wl[t], wl[t]);
                const ulonglong2* sr =
                    (const ulonglong2*)(samp + (jj * 4 + t) * PIX2);
#pragma unroll
                for (int q = 0; q < 16; ++q) {
                    ulonglong2 s = sr[q];
                    fma2(acc[2 * q],     w2, s.x);
                    fma2(acc[2 * q + 1], w2, s.y);
                }
            }
        }
        __syncthreads();
    }

    // ---- epilogue: write full row of y ----
    float* yb = g_y + ((size_t)(bimg * COUT_ + tid)) * HW_ + h * W_;
#pragma unroll
    for (int q = 0; q < 16; ++q) {
        float2 a = unpack2(acc[2 * q]);
        float2 b = unpack2(acc[2 * q + 1]);
        *(float4*)(yb + 4 * q) = make_float4(a.x, a.y, b.x, b.y);
    }
}

// ===========================================================================
// Kernel 3: BN batch stats -> g_scale/g_shift. One block per channel.
// ===========================================================================
__global__ __launch_bounds__(256)
void k_stats(const float* __restrict__ gamma, const float* __restrict__ beta) {
    const int co = blockIdx.x;
    const int t  = threadIdx.x;
    float s = 0.f, s2 = 0.f;
    for (int b = 0; b < B_; ++b) {
        const float* yb = g_y + ((size_t)(b * COUT_ + co)) * HW_;
        for (int i = t * 4; i < HW_; i += 1024) {
            float4 v = *(const float4*)(yb + i);
            s  += v.x + v.y + v.z + v.w;
            s2 += v.x * v.x + v.y * v.y + v.z * v.z + v.w * v.w;
        }
    }
    __shared__ float rs[256], rq[256];
    rs[t] = s; rq[t] = s2;
    __syncthreads();
    for (int off = 128; off; off >>= 1) {
        if (t < off) { rs[t] += rs[t + off]; rq[t] += rq[t + off]; }
        __syncthreads();
    }
    if (t == 0) {
        const float inv_n = 1.f / (float)(B_ * HW_);
        float mean = rs[0] * inv_n;
        float var  = rq[0] * inv_n - mean * mean;
        float istd = rsqrtf(var + EPS_);
        float g = gamma[co];
        g_scale[co] = g * istd;
        g_shift[co] = beta[co] - mean * g * istd;
    }
}

// ===========================================================================
// Kernel 4: normalize + 1x1 shortcut + relu -> out
// One block = one (image,row): 64 pixels. 256 threads (thread = cout). occ 2.
// ===========================================================================
__global__ __launch_bounds__(256, 2)
void k_final(const float* __restrict__ x, const float* __restrict__ w_sc,
             const float* __restrict__ b_sc, float* __restrict__ out) {
    __shared__ __align__(16) float xs[CIN_ * PIX2];   // [c][64], 32KB

    const int tid  = threadIdx.x;
    const int blk  = blockIdx.x;       // 0..511
    const int bimg = blk >> 6;
    const int h    = blk & 63;

    // cooperative load of x[b, :, h, :]  (128 rows of 64 floats)
    const float* xb = x + ((size_t)bimg * CIN_) * HW_ + h * W_;
#pragma unroll
    for (int i = 0; i < 8; ++i) {
        int e4 = tid + i * 256;        // float4 index, 2048 total
        int c  = e4 >> 4;              // 16 float4 per row
        int p4 = e4 & 15;
        *(float4*)(xs + c * PIX2 + p4 * 4) =
            *(const float4*)(xb + (size_t)c * HW_ + p4 * 4);
    }

    unsigned long long acc[32];
    {
        float bias = __ldg(b_sc + tid);
        unsigned long long b2 = pack2(bias, bias);
#pragma unroll
        for (int m = 0; m < 32; ++m) acc[m] = b2;
    }
    __syncthreads();

    const float4* wrow4 = (const float4*)(w_sc + (size_t)tid * CIN_);
#pragma unroll 4
    for (int jj = 0; jj < CIN_ / 4; ++jj) {
        float4 wq = __ldg(wrow4 + jj);
        float wl[4] = {wq.x, wq.y, wq.z, wq.w};
#pragma unroll
        for (int t = 0; t < 4; ++t) {
            unsigned long long w2 = pack2(wl[t], wl[t]);
            const ulonglong2* sr = (const ulonglong2*)(xs + (jj * 4 + t) * PIX2);
#pragma unroll
            for (int q = 0; q < 16; ++q) {
                ulonglong2 s = sr[q];
                fma2(acc[2 * q],     w2, s.x);
                fma2(acc[2 * q + 1], w2, s.y);
            }
        }
    }

    const float sc = g_scale[tid];
    const float sh = g_shift[tid];
    const size_t o = ((size_t)(bimg * COUT_ + tid)) * HW_ + h * W_;
#pragma unroll
    for (int q = 0; q < 16; ++q) {
        float4 yv = *(const float4*)(g_y + o + 4 * q);
        float2 a = unpack2(acc[2 * q]);
        float2 b = unpack2(acc[2 * q + 1]);
        float4 r;
        r.x = fmaxf(yv.x * sc + sh + a.x, 0.f);
        r.y = fmaxf(yv.y * sc + sh + a.y, 0.f);
        r.z = fmaxf(yv.z * sc + sh + b.x, 0.f);
        r.w = fmaxf(yv.w * sc + sh + b.y, 0.f);
        *(float4*)(out + o + 4 * q) = r;
    }
}

// ===========================================================================
extern "C" void kernel_launch(void* const* d_in, const int* in_sizes, int n_in,
                              void* d_out, int out_size) {
    const float* x     = (const float*)d_in[0];
    const float* w_off = (const float*)d_in[1];
    const float* b_off = (const float*)d_in[2];
    const float* w_def = (const float*)d_in[3];
    const float* b_def = (const float*)d_in[4];
    const float* gamma = (const float*)d_in[5];
    const float* beta  = (const float*)d_in[6];
    const float* w_sc  = (const float*)d_in[7];
    const float* b_sc  = (const float*)d_in[8];
    float* out = (float*)d_out;

    const int smem1 = (20736 + 6 * 66) * 4;                       // ~84.6 KB
    const int smem2 = KCH * PIX2 * 4
                    + PIX2 * 9 * (sizeof(int4) + sizeof(float4)); // ~36.9 KB

    cudaFuncSetAttribute(k_offset, cudaFuncAttributeMaxDynamicSharedMemorySize, smem1);
    cudaFuncSetAttribute(k_main,   cudaFuncAttributeMaxDynamicSharedMemorySize, smem2);

    k_offset<<<dim3(16, 8), 256, smem1>>>(x, w_off, b_off);
    k_main<<<512, 256, smem2>>>(x, w_def, b_def);
    k_stats<<<256, 256>>>(gamma, beta);
    k_final<<<512, 256>>>(x, w_sc, b_sc, out);
}

// round 6
// speedup vs baseline: 2.0185x; 1.8559x over previous
#include <cuda_runtime.h>
#include <cuda_bf16.h>
#include <cstdint>

// ---------------------------------------------------------------------------
// DeformableConvBlock: offset conv -> deformable sample+conv (HMMA bf16x3)
//                      -> BN -> +1x1 shortcut -> relu
// B=8, CIN=128, COUT=256, H=W=64
// ---------------------------------------------------------------------------

#define B_    8
#define CIN_  128
#define COUT_ 256
#define H_    64
#define W_    64
#define HW_   4096
#define KTOT  1152           // CIN*9
#define EPS_  1e-5f
#define NPIX_ 32768          // B*H*W

// ---- device scratch (allocation-free rule) ----
__device__ float g_off[B_ * 18 * HW_];                        // offsets
__device__ float g_y[B_ * COUT_ * HW_];                       // pre-BN main out
__device__ float g_scale[COUT_];
__device__ float g_shift[COUT_];
__device__ __align__(128) unsigned g_w[COUT_ * KTOT];         // w_def hi16|lo16
__device__ __align__(128) unsigned g_s[(size_t)NPIX_ * KTOT]; // im2col hi16|lo16

// ---- f32x2 helpers (scalar kernels) ----
__device__ __forceinline__ unsigned long long pack2(float a, float b) {
    unsigned long long r;
    asm("mov.b64 %0, {%1, %2};" : "=l"(r)
        : "r"(__float_as_uint(a)), "r"(__float_as_uint(b)));
    return r;
}
__device__ __forceinline__ float2 unpack2(unsigned long long v) {
    unsigned int a, b;
    asm("mov.b64 {%0, %1}, %2;" : "=r"(a), "=r"(b) : "l"(v));
    return make_float2(__uint_as_float(a), __uint_as_float(b));
}
__device__ __forceinline__ void fma2(unsigned long long& d,
                                     unsigned long long a, unsigned long long b) {
    asm("fma.rn.f32x2 %0, %1, %2, %0;" : "+l"(d) : "l"(a), "l"(b));
}

// ---- HMMA: m16n8k16 row.col f32.bf16.bf16.f32 ----
__device__ __forceinline__ void hmma(float* c, const unsigned* a, const unsigned* b) {
    asm("mma.sync.aligned.m16n8k16.row.col.f32.bf16.bf16.f32 "
        "{%0,%1,%2,%3}, {%4,%5,%6,%7}, {%8,%9}, {%0,%1,%2,%3};"
        : "+f"(c[0]), "+f"(c[1]), "+f"(c[2]), "+f"(c[3])
        : "r"(a[0]), "r"(a[1]), "r"(a[2]), "r"(a[3]), "r"(b[0]), "r"(b[1]));
}

// ===========================================================================
// Kernel 1: offset conv  (3x3, pad 1, CIN=128 -> 18)
// ===========================================================================
__global__ __launch_bounds__(256, 1)
void k_offset(const float* __restrict__ x, const float* __restrict__ w_off,
              const float* __restrict__ b_off) {
    extern __shared__ float sm1[];
    float* ws = sm1;                 // 20736 floats
    float* xt = sm1 + 20736;         // [6][66]

    const int tid = threadIdx.x;
    const int b   = blockIdx.y;
    const int h0  = blockIdx.x * 4;

    for (int i = tid; i < 18 * CIN_ * 9; i += 256) {
        int co  = i / (CIN_ * 9);
        int r   = i - co * (CIN_ * 9);
        int cin = r / 9;
        int k   = r - cin * 9;
        ws[(cin * 9 + k) * 18 + co] = w_off[i];
    }
    __syncthreads();

    const int rt = tid >> 6;
    const int wc = tid & 63;

    unsigned long long acc[9];
#pragma unroll
    for (int m = 0; m < 9; ++m) acc[m] = 0ull;

    const float* xb = x + ((size_t)b * CIN_) * HW_;

    for (int cin = 0; cin < CIN_; ++cin) {
        const float* xc = xb + (size_t)cin * HW_;
        for (int i = tid; i < 6 * 66; i += 256) {
            int r  = i / 66;
            int cc = i - r * 66;
            int gy = h0 - 1 + r;
            int gx = cc - 1;
            float v = 0.f;
            if (gy >= 0 && gy < H_ && gx >= 0 && gx < W_) v = xc[gy * W_ + gx];
            xt[i] = v;
        }
        __syncthreads();

        float xv[9];
#pragma unroll
        for (int ky = 0; ky < 3; ++ky)
#pragma unroll
            for (int kx = 0; kx < 3; ++kx)
                xv[ky * 3 + kx] = xt[(rt + ky) * 66 + (wc + kx)];

#pragma unroll
        for (int k = 0; k < 9; ++k) {
            const unsigned long long* wp =
                (const unsigned long long*)(ws) + (size_t)(cin * 9 + k) * 9;
            unsigned long long x2 = pack2(xv[k], xv[k]);
#pragma unroll
            for (int m = 0; m < 9; ++m) fma2(acc[m], wp[m], x2);
        }
        __syncthreads();
    }

    float* ob = g_off + ((size_t)b * 18) * HW_ + (h0 + rt) * W_ + wc;
#pragma unroll
    for (int m = 0; m < 9; ++m) {
        float2 v = unpack2(acc[m]);
        ob[(2 * m) * HW_]     = v.x + b_off[2 * m];
        ob[(2 * m + 1) * HW_] = v.y + b_off[2 * m + 1];
    }
}

// ===========================================================================
// Kernel 2: split w_def into packed bf16 hi|lo
// ===========================================================================
__global__ __launch_bounds__(1024)
void k_wsplit(const float* __restrict__ w) {
    int i = blockIdx.x * 1024 + threadIdx.x;
    float v = w[i];
    __nv_bfloat16 h = __float2bfloat16(v);
    float vh = __bfloat162float(h);
    __nv_bfloat16 l = __float2bfloat16(v - vh);
    g_w[i] = ((unsigned)__bfloat16_as_ushort(h) << 16)
           | (unsigned)__bfloat16_as_ushort(l);
}

// ===========================================================================
// Kernel 3: im2col — deformable bilinear gather -> packed bf16 hi|lo,
// S layout [pixel][1152]. Block = (image,row) = 64 pixels, 256 threads.
// ===========================================================================
#define ICH  32              // cins per chunk
#define IKC  (ICH * 9)       // 288 k per chunk

__global__ __launch_bounds__(256, 2)
void k_im2col(const float* __restrict__ x) {
    extern __shared__ float smI[];
    float*  samp  = smI;                               // [288][65]
    int4*   tap_a = (int4*)(smI + IKC * 65);           // 576
    float4* tap_w = (float4*)(tap_a + 64 * 9);         // 576

    const int tid  = threadIdx.x;
    const int wid  = tid >> 5;
    const int lid  = tid & 31;
    const int blk  = blockIdx.x;       // 0..511
    const int bimg = blk >> 6;
    const int h    = blk & 63;

    for (int idx = tid; idx < 64 * 9; idx += 256) {
        int p = idx / 9;
        int k = idx - p * 9;
        const float* offb = g_off + ((size_t)bimg * 18) * HW_ + h * W_ + p;
        float dy = offb[(size_t)(2 * k) * HW_];
        float dx = offb[(size_t)(2 * k + 1) * HW_];
        float py = (float)(h + (k / 3) - 1) + dy;
        float px = (float)(p + (k % 3) - 1) + dx;
        float y0 = floorf(py), x0 = floorf(px);
        float fy = py - y0,    fx = px - x0;
        int iy = (int)y0, ix = (int)x0;
        float w00 = (1.f - fy) * (1.f - fx);
        float w01 = (1.f - fy) * fx;
        float w10 = fy * (1.f - fx);
        float w11 = fy * fx;
        int4 ad; float4 wt;
        bool vy0 = (iy >= 0)     && (iy < H_);
        bool vy1 = (iy + 1 >= 0) && (iy + 1 < H_);
        bool vx0 = (ix >= 0)     && (ix < W_);
        bool vx1 = (ix + 1 >= 0) && (ix + 1 < W_);
        ad.x = (vy0 && vx0) ? (iy * W_ + ix)           : 0;  wt.x = (vy0 && vx0) ? w00 : 0.f;
        ad.y = (vy0 && vx1) ? (iy * W_ + ix + 1)       : 0;  wt.y = (vy0 && vx1) ? w01 : 0.f;
        ad.z = (vy1 && vx0) ? ((iy + 1) * W_ + ix)     : 0;  wt.z = (vy1 && vx0) ? w10 : 0.f;
        ad.w = (vy1 && vx1) ? ((iy + 1) * W_ + ix + 1) : 0;  wt.w = (vy1 && vx1) ? w11 : 0.f;
        tap_a[idx] = ad;
        tap_w[idx] = wt;
    }
    __syncthreads();

    const float* xb = x + ((size_t)bimg * CIN_) * HW_;
    const size_t rowbase = (size_t)(bimg * HW_ + h * W_) * KTOT;

    for (int c0 = 0; c0 < CIN_; c0 += ICH) {
        // gather chunk: 288 k x 64 px, pixel-coalesced
#pragma unroll 4
        for (int i = 0; i < IKC * 64 / 256; ++i) {
            int e  = i * 256 + tid;
            int p  = e & 63;
            int kk = e >> 6;              // 0..287
            int c  = kk / 9;
            int k  = kk - c * 9;
            int ti = p * 9 + k;
            int4   ad = tap_a[ti];
            float4 wt = tap_w[ti];
            const float* xc = xb + (size_t)(c0 + c) * HW_;
            samp[kk * 65 + p] = wt.x * __ldg(xc + ad.x) + wt.y * __ldg(xc + ad.y)
                              + wt.z * __ldg(xc + ad.z) + wt.w * __ldg(xc + ad.w);
        }
        __syncthreads();

        // transposed writeout: warp owns 8 pixels; lanes sweep k (coalesced STG)
        for (int pi = 0; pi < 8; ++pi) {
            int p = wid * 8 + pi;
            unsigned* row = g_s + rowbase + (size_t)p * KTOT + c0 * 9;
#pragma unroll
            for (int pass = 0; pass < 9; ++pass) {
                int k = pass * 32 + lid;
                float v = samp[k * 65 + p];
                __nv_bfloat16 hh = __float2bfloat16(v);
                float vh = __bfloat162float(hh);
                __nv_bfloat16 ll = __float2bfloat16(v - vh);
                row[k] = ((unsigned)__bfloat16_as_ushort(hh) << 16)
                       | (unsigned)__bfloat16_as_ushort(ll);
            }
        }
        __syncthreads();
    }
}

// ===========================================================================
// Kernel 4: HMMA GEMM  g_y[cout][pixel] = W[cout][K] * S[pixel][K] + bias
// Block tile M=128 x N=64, Kc=64. 8 warps (4M x 2N), warp tile 32x32.
// 3-product bf16 split accumulated in fp32.
// smem planes padded to 72 bf16/row (144B) -> conflict-free LDS.32 frags.
// ===========================================================================
#define KC   64
#define APAD 72
// ushort offsets into dynamic smem
#define SA_HI 0
#define SA_LO (128 * APAD)
#define SB_HI (2 * 128 * APAD)
#define SB_LO (2 * 128 * APAD + 64 * APAD)
#define SMEMG_USHORT (2 * 128 * APAD + 2 * 64 * APAD)   // 27648 ushorts = 55296 B

__global__ __launch_bounds__(256, 2)
void k_gemm(const float* __restrict__ b_def) {
    extern __shared__ ushort smU[];

    const int tid   = threadIdx.x;
    const int lane  = tid & 31;
    const int wid   = tid >> 5;
    const int wm    = wid & 3;          // warp row (M)
    const int wn    = wid >> 2;         // warp col (N)

    const int ntile = blockIdx.x;       // 0..511 (64-pixel tiles)
    const int mtile = blockIdx.y;       // 0..1   (128-cout tiles)
    const int pix0  = ntile * 64;
    const int bimg  = pix0 >> 12;
    const int poff  = pix0 & 4095;

    const unsigned* srcA = g_w + (size_t)(mtile * 128) * KTOT;
    const unsigned* srcB = g_s + (size_t)pix0 * KTOT;

    float acc[2][4][4];
#pragma unroll
    for (int mf = 0; mf < 2; ++mf)
#pragma unroll
        for (int nf = 0; nf < 4; ++nf)
#pragma unroll
            for (int q = 0; q < 4; ++q) acc[mf][nf][q] = 0.f;

    const int rquad = lane >> 2;        // 0..7
    const int kcol  = (lane & 3) * 2;   // 0,2,4,6

    for (int ch = 0; ch < KTOT / KC; ++ch) {
        const int k0 = ch * KC;

        // ---- stage A tile: 128 rows x 64 u32 ----
#pragma unroll
        for (int it = 0; it < 8; ++it) {
            int idx4 = tid + it * 256;          // 0..2047
            int r    = idx4 >> 4;
            int j4   = idx4 & 15;
            uint4 q = *(const uint4*)(srcA + (size_t)r * KTOT + k0 + j4 * 4);
            unsigned hi01 = __byte_perm(q.x, q.y, 0x7632);
            unsigned lo01 = __byte_perm(q.x, q.y, 0x5410);
            unsigned hi23 = __byte_perm(q.z, q.w, 0x7632);
            unsigned lo23 = __byte_perm(q.z, q.w, 0x5410);
            ushort* dh = smU + SA_HI + r * APAD + j4 * 4;
            ushort* dl = smU + SA_LO + r * APAD + j4 * 4;
            *(unsigned*)(dh)     = hi01;
            *(unsigned*)(dh + 2) = hi23;
            *(unsigned*)(dl)     = lo01;
            *(unsigned*)(dl + 2) = lo23;
        }
        // ---- stage B tile: 64 rows x 64 u32 ----
#pragma unroll
        for (int it = 0; it < 4; ++it) {
            int idx4 = tid + it * 256;          // 0..1023
            int r    = idx4 >> 4;
            int j4   = idx4 & 15;
            uint4 q = *(const uint4*)(srcB + (size_t)r * KTOT + k0 + j4 * 4);
            unsigned hi01 = __byte_perm(q.x, q.y, 0x7632);
            unsigned lo01 = __byte_perm(q.x, q.y, 0x5410);
            unsigned hi23 = __byte_perm(q.z, q.w, 0x7632);
            unsigned lo23 = __byte_perm(q.z, q.w, 0x5410);
            ushort* dh = smU + SB_HI + r * APAD + j4 * 4;
            ushort* dl = smU + SB_LO + r * APAD + j4 * 4;
            *(unsigned*)(dh)     = hi01;
            *(unsigned*)(dh + 2) = hi23;
            *(unsigned*)(dl)     = lo01;
            *(unsigned*)(dl + 2) = lo23;
        }
        __syncthreads();

        // ---- 4 k-steps of m16n8k16 ----
#pragma unroll
        for (int ks = 0; ks < 4; ++ks) {
            const int kk = ks * 16 + kcol;

            unsigned aH[2][4], aL[2][4];
#pragma unroll
            for (int mf = 0; mf < 2; ++mf) {
                int r0 = wm * 32 + mf * 16 + rquad;
                const ushort* ph = smU + SA_HI + r0 * APAD + kk;
                const ushort* pl = smU + SA_LO + r0 * APAD + kk;
                aH[mf][0] = *(const unsigned*)(ph);
                aH[mf][1] = *(const unsigned*)(ph + 8 * APAD);
                aH[mf][2] = *(const unsigned*)(ph + 8);
                aH[mf][3] = *(const unsigned*)(ph + 8 * APAD + 8);
                aL[mf][0] = *(const unsigned*)(pl);
                aL[mf][1] = *(const unsigned*)(pl + 8 * APAD);
                aL[mf][2] = *(const unsigned*)(pl + 8);
                aL[mf][3] = *(const unsigned*)(pl + 8 * APAD + 8);
            }
            unsigned bH[4][2], bL[4][2];
#pragma unroll
            for (int nf = 0; nf < 4; ++nf) {
                int r0 = wn * 32 + nf * 8 + rquad;
                const ushort* ph = smU + SB_HI + r0 * APAD + kk;
                const ushort* pl = smU + SB_LO + r0 * APAD + kk;
                bH[nf][0] = *(const unsigned*)(ph);
                bH[nf][1] = *(const unsigned*)(ph + 8);
                bL[nf][0] = *(const unsigned*)(pl);
                bL[nf][1] = *(const unsigned*)(pl + 8);
            }
#pragma unroll
            for (int mf = 0; mf < 2; ++mf)
#pragma unroll
                for (int nf = 0; nf < 4; ++nf) {
                    hmma(acc[mf][nf], aH[mf], bH[nf]);
                    hmma(acc[mf][nf], aH[mf], bL[nf]);
                    hmma(acc[mf][nf], aL[mf], bH[nf]);
                }
        }
        __syncthreads();
    }

    // ---- epilogue: bias + store to g_y ----
#pragma unroll
    for (int mf = 0; mf < 2; ++mf) {
#pragma unroll
        for (int hr = 0; hr < 2; ++hr) {
            int cout = mtile * 128 + wm * 32 + mf * 16 + rquad + hr * 8;
            float bias = __ldg(b_def + cout);
            float* dst = g_y + ((size_t)(bimg * COUT_ + cout)) * HW_
                       + poff + wn * 32 + (lane & 3) * 2;
#pragma unroll
            for (int nf = 0; nf < 4; ++nf) {
                float2 v;
                v.x = acc[mf][nf][hr * 2 + 0] + bias;
                v.y = acc[mf][nf][hr * 2 + 1] + bias;
                *(float2*)(dst + nf * 8) = v;
            }
        }
    }
}

// ===========================================================================
// Kernel 5: BN batch stats
// ===========================================================================
__global__ __launch_bounds__(256)
void k_stats(const float* __restrict__ gamma, const float* __restrict__ beta) {
    const int co = blockIdx.x;
    const int t  = threadIdx.x;
    float s = 0.f, s2 = 0.f;
    for (int b = 0; b < B_; ++b) {
        const float* yb = g_y + ((size_t)(b * COUT_ + co)) * HW_;
        for (int i = t * 4; i < HW_; i += 1024) {
            float4 v = *(const float4*)(yb + i);
            s  += v.x + v.y + v.z + v.w;
            s2 += v.x * v.x + v.y * v.y + v.z * v.z + v.w * v.w;
        }
    }
    __shared__ float rs[256], rq[256];
    rs[t] = s; rq[t] = s2;
    __syncthreads();
    for (int off = 128; off; off >>= 1) {
        if (t < off) { rs[t] += rs[t + off]; rq[t] += rq[t + off]; }
        __syncthreads();
    }
    if (t == 0) {
        const float inv_n = 1.f / (float)(B_ * HW_);
        float mean = rs[0] * inv_n;
        float var  = rq[0] * inv_n - mean * mean;
        float istd = rsqrtf(var + EPS_);
        float g = gamma[co];
        g_scale[co] = g * istd;
        g_shift[co] = beta[co] - mean * g * istd;
    }
}

// ===========================================================================
// Kernel 6: normalize + 1x1 shortcut + relu.
// Block = (image,row). Thread = 2 adjacent couts x 32 pixels.
// ===========================================================================
__global__ __launch_bounds__(256, 2)
void k_final(const float* __restrict__ x, const float* __restrict__ w_sc,
             const float* __restrict__ b_sc, float* __restrict__ out) {
    __shared__ __align__(16) float xs[CIN_ * 64];

    const int tid  = threadIdx.x;
    const int cp   = tid & 127;          // cout pair index
    const int half = tid >> 7;           // pixel half
    const int blk  = blockIdx.x;
    const int bimg = blk >> 6;
    const int h    = blk & 63;

    const float* xb = x + ((size_t)bimg * CIN_) * HW_ + h * W_;
#pragma unroll
    for (int i = 0; i < 8; ++i) {
        int e4 = tid + i * 256;
        int c  = e4 >> 4;
        int p4 = e4 & 15;
        *(float4*)(xs + c * 64 + p4 * 4) =
            *(const float4*)(xb + (size_t)c * HW_ + p4 * 4);
    }

    const int co0 = cp * 2;
    unsigned long long a0[16], a1[16];
    {
        float b0v = __ldg(b_sc + co0);
        float b1v = __ldg(b_sc + co0 + 1);
        unsigned long long p0 = pack2(b0v, b0v), p1 = pack2(b1v, b1v);
#pragma unroll
        for (int m = 0; m < 16; ++m) { a0[m] = p0; a1[m] = p1; }
    }
    __syncthreads();

    const float4* w0 = (const float4*)(w_sc + (size_t)co0 * CIN_);
    const float4* w1 = (const float4*)(w_sc + (size_t)(co0 + 1) * CIN_);
#pragma unroll 4
    for (int jj = 0; jj < CIN_ / 4; ++jj) {
        float4 q0 = __ldg(w0 + jj);
        float4 q1 = __ldg(w1 + jj);
        float l0[4] = {q0.x, q0.y, q0.z, q0.w};
        float l1[4] = {q1.x, q1.y, q1.z, q1.w};
#pragma unroll
        for (int t = 0; t < 4; ++t) {
            unsigned long long wa = pack2(l0[t], l0[t]);
            unsigned long long wb = pack2(l1[t], l1[t]);
            const ulonglong2* sr =
                (const ulonglong2*)(xs + (jj * 4 + t) * 64 + half * 32);
#pragma unroll
            for (int q = 0; q < 8; ++q) {
                ulonglong2 s = sr[q];
                fma2(a0[2 * q],     wa, s.x);
                fma2(a0[2 * q + 1], wa, s.y);
                fma2(a1[2 * q],     wb, s.x);
                fma2(a1[2 * q + 1], wb, s.y);
            }
        }
    }

#pragma unroll
    for (int cc = 0; cc < 2; ++cc) {
        const int co = co0 + cc;
        const float sc = g_scale[co];
        const float sh = g_shift[co];
        const size_t o = ((size_t)(bimg * COUT_ + co)) * HW_ + h * W_ + half * 32;
        const unsigned long long* aa = cc ? a1 : a0;
#pragma unroll
        for (int q = 0; q < 8; ++q) {
            float4 yv = *(const float4*)(g_y + o + 4 * q);
            float2 a = unpack2(aa[2 * q]);
            float2 b = unpack2(aa[2 * q + 1]);
            float4 r;
            r.x = fmaxf(yv.x * sc + sh + a.x, 0.f);
            r.y = fmaxf(yv.y * sc + sh + a.y, 0.f);
            r.z = fmaxf(yv.z * sc + sh + b.x, 0.f);
            r.w = fmaxf(yv.w * sc + sh + b.y, 0.f);
            *(float4*)(out + o + 4 * q) = r;
        }
    }
}

// ===========================================================================
extern "C" void kernel_launch(void* const* d_in, const int* in_sizes, int n_in,
                              void* d_out, int out_size) {
    const float* x     = (const float*)d_in[0];
    const float* w_off = (const float*)d_in[1];
    const float* b_off = (const float*)d_in[2];
    const float* w_def = (const float*)d_in[3];
    const float* b_def = (const float*)d_in[4];
    const float* gamma = (const float*)d_in[5];
    const float* beta  = (const float*)d_in[6];
    const float* w_sc  = (const float*)d_in[7];
    const float* b_sc  = (const float*)d_in[8];
    float* out = (float*)d_out;

    const int smem1 = (20736 + 6 * 66) * 4;
    const int smemI = (IKC * 65) * 4 + 64 * 9 * (sizeof(int4) + sizeof(float4));
    const int smemG = SMEMG_USHORT * 2;   // 55296 bytes

    cudaFuncSetAttribute(k_offset, cudaFuncAttributeMaxDynamicSharedMemorySize, smem1);
    cudaFuncSetAttribute(k_im2col, cudaFuncAttributeMaxDynamicSharedMemorySize, smemI);
    cudaFuncSetAttribute(k_gemm,   cudaFuncAttributeMaxDynamicSharedMemorySize, smemG);

    k_offset<<<dim3(16, 8), 256, smem1>>>(x, w_off, b_off);
    k_wsplit<<<288, 1024>>>(w_def);
    k_im2col<<<512, 256, smemI>>>(x);
    k_gemm<<<dim3(512, 2), 256, smemG>>>(b_def);
    k_stats<<<256, 256>>>(gamma, beta);
    k_final<<<512, 256>>>(x, w_sc, b_sc, out);
}